// round 1
// baseline (speedup 1.0000x reference)
#include <cuda_runtime.h>
#include <math.h>

#define V 50257
#define H 1024
#define E 1024
#define L 512
#define HE 2048
#define G3 3072

// ---------------- scratch (no allocations allowed) ----------------
__device__ float g_attn_logits[L];
__device__ float g_aw[L];
__device__ float g_att[H];
__device__ float g_x[E];
__device__ float g_gi[G3];
__device__ float g_gh[G3];
__device__ float g_h[H];
__device__ float g_logits[V];
__device__ float g_red[2];   // [0]=max, [1]=log(sumexp)

// ---------------- block reduction helpers ----------------
__device__ __forceinline__ float blk_sum(float v, float* s) {
    int lane = threadIdx.x & 31, w = threadIdx.x >> 5;
    #pragma unroll
    for (int o = 16; o; o >>= 1) v += __shfl_down_sync(0xffffffffu, v, o);
    if (lane == 0) s[w] = v;
    __syncthreads();
    int nw = (blockDim.x + 31) >> 5;
    v = (threadIdx.x < nw) ? s[threadIdx.x] : 0.0f;
    if (w == 0) {
        #pragma unroll
        for (int o = 16; o; o >>= 1) v += __shfl_down_sync(0xffffffffu, v, o);
    }
    __syncthreads();   // make s safely reusable
    return v;          // valid on thread 0
}

__device__ __forceinline__ float blk_max(float v, float* s) {
    int lane = threadIdx.x & 31, w = threadIdx.x >> 5;
    #pragma unroll
    for (int o = 16; o; o >>= 1) v = fmaxf(v, __shfl_down_sync(0xffffffffu, v, o));
    if (lane == 0) s[w] = v;
    __syncthreads();
    int nw = (blockDim.x + 31) >> 5;
    v = (threadIdx.x < nw) ? s[threadIdx.x] : -INFINITY;
    if (w == 0) {
        #pragma unroll
        for (int o = 16; o; o >>= 1) v = fmaxf(v, __shfl_down_sync(0xffffffffu, v, o));
    }
    __syncthreads();
    return v;
}

__device__ __forceinline__ float sigmoidf_(float x) { return 1.0f / (1.0f + expf(-x)); }

// ---------------- 1) attention logits: [emb,h0] @ attn_w.T + attn_b ----------------
// grid = L (512), block = 256. Row = 2048 floats = 2 float4 per thread.
__global__ void k_attn(const int* __restrict__ tok, const float* __restrict__ hidden,
                       const float* __restrict__ embedding,
                       const float* __restrict__ attn_w, const float* __restrict__ attn_b) {
    __shared__ float s[32];
    const int row = blockIdx.x;
    const float* emb = embedding + (size_t)tok[0] * E;
    const float* wr  = attn_w + (size_t)row * HE;
    float acc = 0.0f;
    #pragma unroll
    for (int i = threadIdx.x * 4; i < HE; i += 256 * 4) {
        float4 w4 = *(const float4*)(wr + i);
        float4 x4 = (i < E) ? *(const float4*)(emb + i)
                            : *(const float4*)(hidden + (i - E));
        acc += w4.x * x4.x + w4.y * x4.y + w4.z * x4.z + w4.w * x4.w;
    }
    acc = blk_sum(acc, s);
    if (threadIdx.x == 0) g_attn_logits[row] = acc + attn_b[row];
}

// ---------------- 2) softmax over 512 logits; writes attn_weights output ----------------
// grid = 1, block = 512 (one value per thread)
__global__ void k_softmax(float* __restrict__ out_aw) {
    __shared__ float s[32];
    __shared__ float bm, bs;
    const int t = threadIdx.x;
    float v = g_attn_logits[t];
    float m = blk_max(v, s);
    if (t == 0) bm = m;
    __syncthreads();
    float e = expf(v - bm);
    float sum = blk_sum(e, s);
    if (t == 0) bs = sum;
    __syncthreads();
    float w = e / bs;
    g_aw[t] = w;
    out_aw[t] = w;
}

// ---------------- 3) attn_applied = attn_weights @ encoder_outputs ----------------
// grid = H/256 (4), block = 256; thread owns one output column.
__global__ void k_attnapply(const float* __restrict__ enc) {
    __shared__ float aw[L];
    for (int i = threadIdx.x; i < L; i += blockDim.x) aw[i] = g_aw[i];
    __syncthreads();
    const int col = blockIdx.x * blockDim.x + threadIdx.x;
    float acc = 0.0f;
    #pragma unroll 8
    for (int l = 0; l < L; l++) acc += aw[l] * enc[(size_t)l * H + col];
    g_att[col] = acc;
}

// ---------------- 4) x = relu([emb, attn_applied] @ comb_w.T + comb_b) ----------------
// grid = E (1024), block = 256
__global__ void k_comb(const int* __restrict__ tok, const float* __restrict__ embedding,
                       const float* __restrict__ comb_w, const float* __restrict__ comb_b) {
    __shared__ float s[32];
    const int row = blockIdx.x;
    const float* emb = embedding + (size_t)tok[0] * E;
    const float* wr  = comb_w + (size_t)row * HE;
    float acc = 0.0f;
    #pragma unroll
    for (int i = threadIdx.x * 4; i < HE; i += 256 * 4) {
        float4 w4 = *(const float4*)(wr + i);
        float4 x4 = (i < E) ? *(const float4*)(emb + i)
                            : *(const float4*)(&g_att[i - E]);
        acc += w4.x * x4.x + w4.y * x4.y + w4.z * x4.z + w4.w * x4.w;
    }
    acc = blk_sum(acc, s);
    if (threadIdx.x == 0) g_x[row] = fmaxf(acc + comb_b[row], 0.0f);
}

// ---------------- 5) GRU matvecs: gi = x@w_ih.T + b_ih ; gh = h0@w_hh.T + b_hh ----------------
// grid = 3H (3072), block = 256. Each block does both 1024-dots for its row.
__global__ void k_gru(const float* __restrict__ w_ih, const float* __restrict__ w_hh,
                      const float* __restrict__ b_ih, const float* __restrict__ b_hh,
                      const float* __restrict__ hidden) {
    __shared__ float s[32];
    const int row = blockIdx.x;
    const float* wi = w_ih + (size_t)row * H;
    const float* wh = w_hh + (size_t)row * H;
    const int i = threadIdx.x * 4;   // 256*4 = 1024, exactly one float4 per thread
    float4 a4 = *(const float4*)(wi + i);
    float4 x4 = *(const float4*)(&g_x[i]);
    float4 b4 = *(const float4*)(wh + i);
    float4 h4 = *(const float4*)(hidden + i);
    float ai = a4.x * x4.x + a4.y * x4.y + a4.z * x4.z + a4.w * x4.w;
    float ah = b4.x * h4.x + b4.y * h4.y + b4.z * h4.z + b4.w * h4.w;
    ai = blk_sum(ai, s);
    ah = blk_sum(ah, s);
    if (threadIdx.x == 0) {
        g_gi[row] = ai + b_ih[row];
        g_gh[row] = ah + b_hh[row];
    }
}

// ---------------- 6) GRU gate combine -> h_new ----------------
// grid = H/256 (4), block = 256. Writes h_new output + scratch.
__global__ void k_hnew(const float* __restrict__ hidden, float* __restrict__ out_h) {
    const int j = blockIdx.x * blockDim.x + threadIdx.x;
    float r = sigmoidf_(g_gi[j]         + g_gh[j]);
    float z = sigmoidf_(g_gi[H + j]     + g_gh[H + j]);
    float n = tanhf(g_gi[2 * H + j] + r * g_gh[2 * H + j]);
    float h = (1.0f - z) * n + z * hidden[j];
    g_h[j]  = h;
    out_h[j] = h;
}

// ---------------- 7) logits = h_new @ out_w.T + out_b  (the 206 MB matvec) ----------------
// grid = V (50257), block = 256; one float4 per thread covers the 1024-row exactly.
__global__ void k_logits(const float* __restrict__ out_w, const float* __restrict__ out_b) {
    __shared__ float s[32];
    const int row = blockIdx.x;
    const float* wr = out_w + (size_t)row * H;
    const int i = threadIdx.x * 4;
    float4 w4 = *(const float4*)(wr + i);
    float4 h4 = *(const float4*)(&g_h[i]);
    float acc = w4.x * h4.x + w4.y * h4.y + w4.z * h4.z + w4.w * h4.w;
    acc = blk_sum(acc, s);
    if (threadIdx.x == 0) g_logits[row] = acc + out_b[row];
}

// ---------------- 8) log-sum-exp over V (single block, deterministic) ----------------
// grid = 1, block = 1024. Logits are hot in L2 (200 KB).
__global__ void k_lse() {
    __shared__ float s[32];
    __shared__ float bm;
    float m = -INFINITY;
    for (int v = threadIdx.x; v < V; v += 1024) m = fmaxf(m, g_logits[v]);
    m = blk_max(m, s);
    if (threadIdx.x == 0) bm = m;
    __syncthreads();
    float m0 = bm;
    float sum = 0.0f;
    for (int v = threadIdx.x; v < V; v += 1024) sum += expf(g_logits[v] - m0);
    sum = blk_sum(sum, s);
    if (threadIdx.x == 0) {
        g_red[0] = m0;
        g_red[1] = logf(sum);
    }
}

// ---------------- 9) final log-softmax write ----------------
__global__ void k_out(float* __restrict__ out) {
    const int v = blockIdx.x * blockDim.x + threadIdx.x;
    if (v < V) out[v] = g_logits[v] - g_red[0] - g_red[1];
}

// ---------------- launch ----------------
extern "C" void kernel_launch(void* const* d_in, const int* in_sizes, int n_in,
                              void* d_out, int out_size) {
    const int*   tok       = (const int*)  d_in[0];
    const float* hidden    = (const float*)d_in[1];
    const float* enc       = (const float*)d_in[2];
    const float* embedding = (const float*)d_in[3];
    const float* attn_w    = (const float*)d_in[4];
    const float* attn_b    = (const float*)d_in[5];
    const float* comb_w    = (const float*)d_in[6];
    const float* comb_b    = (const float*)d_in[7];
    const float* w_ih      = (const float*)d_in[8];
    const float* w_hh      = (const float*)d_in[9];
    const float* b_ih      = (const float*)d_in[10];
    const float* b_hh      = (const float*)d_in[11];
    const float* out_w     = (const float*)d_in[12];
    const float* out_b     = (const float*)d_in[13];
    float* out = (float*)d_out;

    // output layout: [log_softmax (V)] [h_new (H)] [attn_weights (L)]
    k_attn     <<<L, 256>>>(tok, hidden, embedding, attn_w, attn_b);
    k_softmax  <<<1, 512>>>(out + V + H);
    k_attnapply<<<H / 256, 256>>>(enc);
    k_comb     <<<E, 256>>>(tok, embedding, comb_w, comb_b);
    k_gru      <<<G3, 256>>>(w_ih, w_hh, b_ih, b_hh, hidden);
    k_hnew     <<<H / 256, 256>>>(hidden, out + V);
    k_logits   <<<V, 256>>>(out_w, out_b);
    k_lse      <<<1, 1024>>>();
    k_out      <<<(V + 255) / 256, 256>>>(out);
}

// round 4
// speedup vs baseline: 1.8770x; 1.8770x over previous
#include <cuda_runtime.h>
#include <math.h>

#define V 50257
#define H 1024
#define E 1024
#define L 512
#define HE 2048
#define G3 3072
#define NP 16            // L-partitions for attn-apply

// ---------------- scratch (no allocations allowed) ----------------
__device__ float g_attn_logits[L];
__device__ float g_aw[L];
__device__ float g_att_part[NP * H];
__device__ float g_x[E];
__device__ float g_gi[G3];
__device__ float g_gh[G3];
__device__ float g_h[H];
__device__ float g_logits[V];
__device__ float g_pmax[64];
__device__ float g_psum[64];
__device__ float g_red[2];   // [0]=max, [1]=log(sumexp)

__device__ __forceinline__ float warp_sum(float v) {
    #pragma unroll
    for (int o = 16; o; o >>= 1) v += __shfl_down_sync(0xffffffffu, v, o);
    return v;
}
__device__ __forceinline__ float warp_max(float v) {
    #pragma unroll
    for (int o = 16; o; o >>= 1) v = fmaxf(v, __shfl_down_sync(0xffffffffu, v, o));
    return v;
}
__device__ __forceinline__ float blk_sum(float v, float* s) {
    int lane = threadIdx.x & 31, w = threadIdx.x >> 5;
    v = warp_sum(v);
    if (lane == 0) s[w] = v;
    __syncthreads();
    int nw = (blockDim.x + 31) >> 5;
    v = (threadIdx.x < nw) ? s[threadIdx.x] : 0.0f;
    if (w == 0) v = warp_sum(v);
    __syncthreads();
    return v;
}
__device__ __forceinline__ float blk_max(float v, float* s) {
    int lane = threadIdx.x & 31, w = threadIdx.x >> 5;
    v = warp_max(v);
    if (lane == 0) s[w] = v;
    __syncthreads();
    int nw = (blockDim.x + 31) >> 5;
    v = (threadIdx.x < nw) ? s[threadIdx.x] : -INFINITY;
    if (w == 0) v = warp_max(v);
    __syncthreads();
    return v;
}
__device__ __forceinline__ float sigmoidf_(float x) { return 1.0f / (1.0f + expf(-x)); }

// ---------------- 1) attention logits: warp-per-row over [emb,h0] (2048) ----------------
// grid = L/8 = 64, block = 256 (8 warps). Each thread: 16 independent float4 loads.
__global__ void k_attn(const int* __restrict__ tok, const float* __restrict__ hidden,
                       const float* __restrict__ embedding,
                       const float* __restrict__ attn_w, const float* __restrict__ attn_b) {
    __shared__ float4 sx[HE / 4];          // 8 KB: [emb, h0]
    const int tid = threadIdx.x;
    {   // stage vector: 512 float4, 256 threads -> 2 each
        const float* emb = embedding + (size_t)tok[0] * E;
        sx[tid]       = *(const float4*)(emb + tid * 4);
        sx[tid + 256] = *(const float4*)(hidden + tid * 4);
    }
    __syncthreads();
    const int warp = tid >> 5, lane = tid & 31;
    const int row = blockIdx.x * 8 + warp;
    const float4* wr = (const float4*)(attn_w + (size_t)row * HE);
    float acc = 0.0f;
    #pragma unroll
    for (int k = 0; k < 16; k++) {
        float4 w4 = wr[lane + 32 * k];
        float4 x4 = sx[lane + 32 * k];
        acc += w4.x * x4.x + w4.y * x4.y + w4.z * x4.z + w4.w * x4.w;
    }
    acc = warp_sum(acc);
    if (lane == 0) g_attn_logits[row] = acc + attn_b[row];
}

// ---------------- 2) softmax over 512 logits; writes attn_weights output ----------------
__global__ void k_softmax(float* __restrict__ out_aw) {
    __shared__ float s[32];
    __shared__ float bm, bs;
    const int t = threadIdx.x;
    float v = g_attn_logits[t];
    float m = blk_max(v, s);
    if (t == 0) bm = m;
    __syncthreads();
    float e = expf(v - bm);
    float sum = blk_sum(e, s);
    if (t == 0) bs = sum;
    __syncthreads();
    float w = e / bs;
    g_aw[t] = w;
    out_aw[t] = w;
}

// ---------------- 3) attn_applied partials: grid (H/256, NP) = 64 blocks ----------------
// block (x,y): cols [256x, 256x+256), rows [32y, 32y+32).
__global__ void k_attnapply(const float* __restrict__ enc) {
    __shared__ float aw[L / NP];
    const int r0 = blockIdx.y * (L / NP);
    if (threadIdx.x < L / NP) aw[threadIdx.x] = g_aw[r0 + threadIdx.x];
    __syncthreads();
    const int col = blockIdx.x * blockDim.x + threadIdx.x;
    float acc = 0.0f;
    #pragma unroll 8
    for (int l = 0; l < L / NP; l++) acc += aw[l] * enc[(size_t)(r0 + l) * H + col];
    g_att_part[blockIdx.y * H + col] = acc;
}

// ---------------- 4) x = relu([emb, att] @ comb_w.T + b): warp-per-row ----------------
// grid = E/8 = 128, block = 256. Partial-combine of att fused into staging.
__global__ void k_comb(const int* __restrict__ tok, const float* __restrict__ embedding,
                       const float* __restrict__ comb_w, const float* __restrict__ comb_b) {
    __shared__ float4 sx[HE / 4];
    const int tid = threadIdx.x;
    {
        const float* emb = embedding + (size_t)tok[0] * E;
        sx[tid] = *(const float4*)(emb + tid * 4);
        // fused combine of NP attn partials for 4 columns
        float4 a = make_float4(0.f, 0.f, 0.f, 0.f);
        #pragma unroll
        for (int p = 0; p < NP; p++) {
            float4 t = *(const float4*)(&g_att_part[p * H + tid * 4]);
            a.x += t.x; a.y += t.y; a.z += t.z; a.w += t.w;
        }
        sx[tid + 256] = a;
    }
    __syncthreads();
    const int warp = tid >> 5, lane = tid & 31;
    const int row = blockIdx.x * 8 + warp;
    const float4* wr = (const float4*)(comb_w + (size_t)row * HE);
    float acc = 0.0f;
    #pragma unroll
    for (int k = 0; k < 16; k++) {
        float4 w4 = wr[lane + 32 * k];
        float4 x4 = sx[lane + 32 * k];
        acc += w4.x * x4.x + w4.y * x4.y + w4.z * x4.z + w4.w * x4.w;
    }
    acc = warp_sum(acc);
    if (lane == 0) g_x[row] = fmaxf(acc + comb_b[row], 0.0f);
}

// ---------------- 5) GRU matvecs: warp-per-row, both matrices ----------------
// grid = 3072/8 = 384, block = 256. Per thread: 8+8 independent float4 loads.
__global__ void k_gru(const float* __restrict__ w_ih, const float* __restrict__ w_hh,
                      const float* __restrict__ b_ih, const float* __restrict__ b_hh,
                      const float* __restrict__ hidden) {
    __shared__ float4 sxv[H / 4];   // x
    __shared__ float4 shv[H / 4];   // h0
    const int tid = threadIdx.x;
    sxv[tid] = *(const float4*)(&g_x[tid * 4]);
    shv[tid] = *(const float4*)(hidden + tid * 4);
    __syncthreads();
    const int warp = tid >> 5, lane = tid & 31;
    const int row = blockIdx.x * 8 + warp;
    const float4* wi = (const float4*)(w_ih + (size_t)row * H);
    const float4* wh = (const float4*)(w_hh + (size_t)row * H);
    float ai = 0.0f, ah = 0.0f;
    #pragma unroll
    for (int k = 0; k < 8; k++) {
        float4 a4 = wi[lane + 32 * k];
        float4 x4 = sxv[lane + 32 * k];
        ai += a4.x * x4.x + a4.y * x4.y + a4.z * x4.z + a4.w * x4.w;
        float4 b4 = wh[lane + 32 * k];
        float4 h4 = shv[lane + 32 * k];
        ah += b4.x * h4.x + b4.y * h4.y + b4.z * h4.z + b4.w * h4.w;
    }
    ai = warp_sum(ai);
    ah = warp_sum(ah);
    if (lane == 0) {
        g_gi[row] = ai + b_ih[row];
        g_gh[row] = ah + b_hh[row];
    }
}

// ---------------- 6) GRU gate combine -> h_new ----------------
__global__ void k_hnew(const float* __restrict__ hidden, float* __restrict__ out_h) {
    const int j = blockIdx.x * blockDim.x + threadIdx.x;
    float r = sigmoidf_(g_gi[j]         + g_gh[j]);
    float z = sigmoidf_(g_gi[H + j]     + g_gh[H + j]);
    float n = tanhf(g_gi[2 * H + j] + r * g_gh[2 * H + j]);
    float h = (1.0f - z) * n + z * hidden[j];
    g_h[j]  = h;
    out_h[j] = h;
}

// ---------------- 7) logits: warp-per-row over 206 MB ----------------
// grid = ceil(V/8) = 6283, block = 256. Per thread: 8 independent float4 loads.
__global__ void k_logits(const float* __restrict__ out_w, const float* __restrict__ out_b) {
    __shared__ float4 shv[H / 4];   // h_new, 4 KB
    const int tid = threadIdx.x;
    shv[tid] = *(const float4*)(&g_h[tid * 4]);
    __syncthreads();
    const int warp = tid >> 5, lane = tid & 31;
    const int row = blockIdx.x * 8 + warp;
    if (row >= V) return;
    const float4* wr = (const float4*)(out_w + (size_t)row * H);
    float acc = 0.0f;
    #pragma unroll
    for (int k = 0; k < 8; k++) {
        float4 w4 = wr[lane + 32 * k];
        float4 h4 = shv[lane + 32 * k];
        acc += w4.x * h4.x + w4.y * h4.y + w4.z * h4.z + w4.w * h4.w;
    }
    acc = warp_sum(acc);
    if (lane == 0) g_logits[row] = acc + out_b[row];
}

// ---------------- 8a) partial log-sum-exp: 64 blocks ----------------
#define LSE_CHUNK 786    // 64*786 = 50304 >= V
__global__ void k_lse1() {
    __shared__ float s[32];
    __shared__ float bm;
    const int b = blockIdx.x;
    const int lo = b * LSE_CHUNK;
    const int hi = min(lo + LSE_CHUNK, V);
    float m = -INFINITY;
    for (int v = lo + threadIdx.x; v < hi; v += blockDim.x) m = fmaxf(m, g_logits[v]);
    m = blk_max(m, s);
    if (threadIdx.x == 0) bm = m;
    __syncthreads();
    float m0 = bm;
    float sum = 0.0f;
    for (int v = lo + threadIdx.x; v < hi; v += blockDim.x) sum += expf(g_logits[v] - m0);
    sum = blk_sum(sum, s);
    if (threadIdx.x == 0) {
        g_pmax[b] = m0;
        g_psum[b] = sum;
    }
}

// ---------------- 8b) combine 64 partials (1 warp) ----------------
__global__ void k_lse2() {
    const int t = threadIdx.x;   // 32 threads, 2 entries each
    float m = fmaxf(g_pmax[t], g_pmax[t + 32]);
    m = warp_max(m);
    m = __shfl_sync(0xffffffffu, m, 0);
    float sum = g_psum[t] * expf(g_pmax[t] - m) + g_psum[t + 32] * expf(g_pmax[t + 32] - m);
    sum = warp_sum(sum);
    if (t == 0) {
        g_red[0] = m;
        g_red[1] = logf(sum);
    }
}

// ---------------- 9) final log-softmax write ----------------
__global__ void k_out(float* __restrict__ out) {
    const int v = blockIdx.x * blockDim.x + threadIdx.x;
    if (v < V) out[v] = g_logits[v] - g_red[0] - g_red[1];
}

// ---------------- launch ----------------
extern "C" void kernel_launch(void* const* d_in, const int* in_sizes, int n_in,
                              void* d_out, int out_size) {
    const int*   tok       = (const int*)  d_in[0];
    const float* hidden    = (const float*)d_in[1];
    const float* enc       = (const float*)d_in[2];
    const float* embedding = (const float*)d_in[3];
    const float* attn_w    = (const float*)d_in[4];
    const float* attn_b    = (const float*)d_in[5];
    const float* comb_w    = (const float*)d_in[6];
    const float* comb_b    = (const float*)d_in[7];
    const float* w_ih      = (const float*)d_in[8];
    const float* w_hh      = (const float*)d_in[9];
    const float* b_ih      = (const float*)d_in[10];
    const float* b_hh      = (const float*)d_in[11];
    const float* out_w     = (const float*)d_in[12];
    const float* out_b     = (const float*)d_in[13];
    float* out = (float*)d_out;

    // output layout: [log_softmax (V)] [h_new (H)] [attn_weights (L)]
    k_attn     <<<L / 8, 256>>>(tok, hidden, embedding, attn_w, attn_b);
    k_softmax  <<<1, 512>>>(out + V + H);
    k_attnapply<<<dim3(H / 256, NP), 256>>>(enc);
    k_comb     <<<E / 8, 256>>>(tok, embedding, comb_w, comb_b);
    k_gru      <<<G3 / 8, 256>>>(w_ih, w_hh, b_ih, b_hh, hidden);
    k_hnew     <<<H / 256, 256>>>(hidden, out + V);
    k_logits   <<<(V + 7) / 8, 256>>>(out_w, out_b);
    k_lse1     <<<64, 256>>>();
    k_lse2     <<<1, 32>>>();
    k_out      <<<(V + 255) / 256, 256>>>(out);
}

// round 6
// speedup vs baseline: 1.9375x; 1.0322x over previous
#include <cuda_runtime.h>
#include <math.h>

#define V 50257
#define H 1024
#define E 1024
#define L 512
#define HE 2048
#define G3 3072
#define NP 16            // L-partitions for attn-apply (32 rows each)

// ---------------- scratch (no allocations allowed) ----------------
__device__ float g_attn_logits[L];
__device__ float g_att_part[NP * H];
__device__ float g_x[E];
__device__ float g_gi[G3];
__device__ float g_gh[G3];
__device__ float g_h[H];
__device__ float g_logits[V];
__device__ float g_pmax[64];
__device__ float g_psum[64];

__device__ __forceinline__ float warp_sum(float v) {
    #pragma unroll
    for (int o = 16; o; o >>= 1) v += __shfl_down_sync(0xffffffffu, v, o);
    return v;
}
__device__ __forceinline__ float warp_max(float v) {
    #pragma unroll
    for (int o = 16; o; o >>= 1) v = fmaxf(v, __shfl_down_sync(0xffffffffu, v, o));
    return v;
}
__device__ __forceinline__ float blk_sum(float v, float* s) {
    int lane = threadIdx.x & 31, w = threadIdx.x >> 5;
    v = warp_sum(v);
    if (lane == 0) s[w] = v;
    __syncthreads();
    int nw = (blockDim.x + 31) >> 5;
    v = (threadIdx.x < nw) ? s[threadIdx.x] : 0.0f;
    if (w == 0) v = warp_sum(v);
    __syncthreads();
    return v;
}
__device__ __forceinline__ float blk_max(float v, float* s) {
    int lane = threadIdx.x & 31, w = threadIdx.x >> 5;
    v = warp_max(v);
    if (lane == 0) s[w] = v;
    __syncthreads();
    int nw = (blockDim.x + 31) >> 5;
    v = (threadIdx.x < nw) ? s[threadIdx.x] : -INFINITY;
    if (w == 0) v = warp_max(v);
    __syncthreads();
    return v;
}
__device__ __forceinline__ float sigmoidf_(float x) { return 1.0f / (1.0f + expf(-x)); }

#define DOT4(a, b) ((a).x * (b).x + (a).y * (b).y + (a).z * (b).z + (a).w * (b).w)

// ---------------- 1) attention logits: warp-per-row over [emb,h0] (2048) ----------------
// grid = L/8 = 64, block = 256. Two explicit 8-load batches -> MLP 8.
__global__ void k_attn(const int* __restrict__ tok, const float* __restrict__ hidden,
                       const float* __restrict__ embedding,
                       const float* __restrict__ attn_w, const float* __restrict__ attn_b) {
    __shared__ float4 sx[HE / 4];          // 8 KB: [emb, h0]
    const int tid = threadIdx.x;
    {
        const float* emb = embedding + (size_t)tok[0] * E;
        sx[tid]       = *(const float4*)(emb + tid * 4);
        sx[tid + 256] = *(const float4*)(hidden + tid * 4);
    }
    __syncthreads();
    const int warp = tid >> 5, lane = tid & 31;
    const int row = blockIdx.x * 8 + warp;
    const float4* wr = (const float4*)(attn_w + (size_t)row * HE);
    float acc = 0.0f;
    float4 w[8];
    #pragma unroll
    for (int k = 0; k < 8; k++) w[k] = wr[lane + 32 * k];
    #pragma unroll
    for (int k = 0; k < 8; k++) { float4 x4 = sx[lane + 32 * k]; acc += DOT4(w[k], x4); }
    #pragma unroll
    for (int k = 0; k < 8; k++) w[k] = wr[lane + 32 * (k + 8)];
    #pragma unroll
    for (int k = 0; k < 8; k++) { float4 x4 = sx[lane + 32 * (k + 8)]; acc += DOT4(w[k], x4); }
    acc = warp_sum(acc);
    if (lane == 0) g_attn_logits[row] = acc + attn_b[row];
}

// ---------------- 2) attn partials with FUSED softmax: grid (H/256, NP) = 64 blocks ----------------
// Each block redundantly computes the 512-wide softmax (cheap), then its 32-row partial.
__global__ void k_attnapply(const float* __restrict__ enc, float* __restrict__ out_aw) {
    __shared__ float s[32];
    __shared__ float sl[L];       // staged logits
    __shared__ float aw[32];      // this block's 32 softmax weights
    __shared__ float bm, bs;
    const int tid = threadIdx.x;
    sl[tid]       = g_attn_logits[tid];
    sl[tid + 256] = g_attn_logits[tid + 256];
    __syncthreads();
    float m = fmaxf(sl[tid], sl[tid + 256]);
    m = blk_max(m, s);
    if (tid == 0) bm = m;
    __syncthreads();
    float e = expf(sl[tid] - bm) + expf(sl[tid + 256] - bm);
    float sum = blk_sum(e, s);
    if (tid == 0) bs = sum;
    __syncthreads();
    const int r0 = blockIdx.y * 32;
    if (tid < 32) {
        float wv = expf(sl[r0 + tid] - bm) / bs;
        aw[tid] = wv;
        if (blockIdx.x == 0) out_aw[r0 + tid] = wv;   // attn_weights output, written once
    }
    __syncthreads();
    const int col = blockIdx.x * blockDim.x + tid;
    float acc = 0.0f;
    #pragma unroll 8
    for (int l = 0; l < 32; l++) acc += aw[l] * enc[(size_t)(r0 + l) * H + col];
    g_att_part[blockIdx.y * H + col] = acc;
}

// ---------------- 3) x = relu([emb, att] @ comb_w.T + b): warp-per-row, batched loads ----------------
// grid = E/8 = 128, block = 256.
__global__ void k_comb(const int* __restrict__ tok, const float* __restrict__ embedding,
                       const float* __restrict__ comb_w, const float* __restrict__ comb_b) {
    __shared__ float4 sx[HE / 4];
    const int tid = threadIdx.x;
    {
        const float* emb = embedding + (size_t)tok[0] * E;
        sx[tid] = *(const float4*)(emb + tid * 4);
        float4 a = make_float4(0.f, 0.f, 0.f, 0.f);
        #pragma unroll
        for (int p = 0; p < NP; p++) {
            float4 t = *(const float4*)(&g_att_part[p * H + tid * 4]);
            a.x += t.x; a.y += t.y; a.z += t.z; a.w += t.w;
        }
        sx[tid + 256] = a;
    }
    __syncthreads();
    const int warp = tid >> 5, lane = tid & 31;
    const int row = blockIdx.x * 8 + warp;
    const float4* wr = (const float4*)(comb_w + (size_t)row * HE);
    float acc = 0.0f;
    float4 w[8];
    #pragma unroll
    for (int k = 0; k < 8; k++) w[k] = wr[lane + 32 * k];
    #pragma unroll
    for (int k = 0; k < 8; k++) { float4 x4 = sx[lane + 32 * k]; acc += DOT4(w[k], x4); }
    #pragma unroll
    for (int k = 0; k < 8; k++) w[k] = wr[lane + 32 * (k + 8)];
    #pragma unroll
    for (int k = 0; k < 8; k++) { float4 x4 = sx[lane + 32 * (k + 8)]; acc += DOT4(w[k], x4); }
    acc = warp_sum(acc);
    if (lane == 0) g_x[row] = fmaxf(acc + comb_b[row], 0.0f);
}

// ---------------- 4) GRU matvecs: warp-per-row, 16 loads in flight ----------------
// grid = 3072/8 = 384, block = 256.
__global__ void k_gru(const float* __restrict__ w_ih, const float* __restrict__ w_hh,
                      const float* __restrict__ b_ih, const float* __restrict__ b_hh,
                      const float* __restrict__ hidden) {
    __shared__ float4 sxv[H / 4];   // x
    __shared__ float4 shv[H / 4];   // h0
    const int tid = threadIdx.x;
    sxv[tid] = *(const float4*)(&g_x[tid * 4]);
    shv[tid] = *(const float4*)(hidden + tid * 4);
    __syncthreads();
    const int warp = tid >> 5, lane = tid & 31;
    const int row = blockIdx.x * 8 + warp;
    const float4* wi = (const float4*)(w_ih + (size_t)row * H);
    const float4* wh = (const float4*)(w_hh + (size_t)row * H);
    float4 a[8], b[8];
    #pragma unroll
    for (int k = 0; k < 8; k++) a[k] = wi[lane + 32 * k];
    #pragma unroll
    for (int k = 0; k < 8; k++) b[k] = wh[lane + 32 * k];
    float ai = 0.0f, ah = 0.0f;
    #pragma unroll
    for (int k = 0; k < 8; k++) {
        float4 x4 = sxv[lane + 32 * k];
        float4 h4 = shv[lane + 32 * k];
        ai += DOT4(a[k], x4);
        ah += DOT4(b[k], h4);
    }
    ai = warp_sum(ai);
    ah = warp_sum(ah);
    if (lane == 0) {
        g_gi[row] = ai + b_ih[row];
        g_gh[row] = ah + b_hh[row];
    }
}

// ---------------- 5) GRU gate combine -> h_new ----------------
__global__ void k_hnew(const float* __restrict__ hidden, float* __restrict__ out_h) {
    const int j = blockIdx.x * blockDim.x + threadIdx.x;
    float r = sigmoidf_(g_gi[j]         + g_gh[j]);
    float z = sigmoidf_(g_gi[H + j]     + g_gh[H + j]);
    float n = tanhf(g_gi[2 * H + j] + r * g_gh[2 * H + j]);
    float h = (1.0f - z) * n + z * hidden[j];
    g_h[j]  = h;
    out_h[j] = h;
}

// ---------------- 6) logits: warp-per-row over 206 MB, batched loads ----------------
// grid = ceil(V/8) = 6283, block = 256.
__global__ void k_logits(const float* __restrict__ out_w, const float* __restrict__ out_b) {
    __shared__ float4 shv[H / 4];   // h_new, 4 KB
    const int tid = threadIdx.x;
    shv[tid] = *(const float4*)(&g_h[tid * 4]);
    __syncthreads();
    const int warp = tid >> 5, lane = tid & 31;
    const int row = blockIdx.x * 8 + warp;
    if (row >= V) return;
    const float4* wr = (const float4*)(out_w + (size_t)row * H);
    float4 w[8];
    #pragma unroll
    for (int k = 0; k < 8; k++) w[k] = wr[lane + 32 * k];
    float acc = 0.0f;
    #pragma unroll
    for (int k = 0; k < 8; k++) { float4 h4 = shv[lane + 32 * k]; acc += DOT4(w[k], h4); }
    acc = warp_sum(acc);
    if (lane == 0) g_logits[row] = acc + out_b[row];
}

// ---------------- 7) partial log-sum-exp: 64 blocks ----------------
#define LSE_CHUNK 786    // 64*786 = 50304 >= V
__global__ void k_lse1() {
    __shared__ float s[32];
    __shared__ float bm;
    const int b = blockIdx.x;
    const int lo = b * LSE_CHUNK;
    const int hi = min(lo + LSE_CHUNK, V);
    float m = -INFINITY;
    for (int v = lo + threadIdx.x; v < hi; v += blockDim.x) m = fmaxf(m, g_logits[v]);
    m = blk_max(m, s);
    if (threadIdx.x == 0) bm = m;
    __syncthreads();
    float m0 = bm;
    float sum = 0.0f;
    for (int v = lo + threadIdx.x; v < hi; v += blockDim.x) sum += expf(g_logits[v] - m0);
    sum = blk_sum(sum, s);
    if (threadIdx.x == 0) {
        g_pmax[b] = m0;
        g_psum[b] = sum;
    }
}

// ---------------- 8) final log-softmax write with FUSED partial combine ----------------
__global__ void k_out(float* __restrict__ out) {
    __shared__ float sm_, sls;
    const int tid = threadIdx.x;
    if (tid < 32) {
        float m = fmaxf(g_pmax[tid], g_pmax[tid + 32]);
        m = warp_max(m);
        m = __shfl_sync(0xffffffffu, m, 0);
        float s2 = g_psum[tid] * expf(g_pmax[tid] - m)
                 + g_psum[tid + 32] * expf(g_pmax[tid + 32] - m);
        s2 = warp_sum(s2);
        if (tid == 0) { sm_ = m; sls = logf(s2); }
    }
    __syncthreads();
    const int v = blockIdx.x * blockDim.x + tid;
    if (v < V) out[v] = g_logits[v] - sm_ - sls;
}

// ---------------- launch ----------------
extern "C" void kernel_launch(void* const* d_in, const int* in_sizes, int n_in,
                              void* d_out, int out_size) {
    const int*   tok       = (const int*)  d_in[0];
    const float* hidden    = (const float*)d_in[1];
    const float* enc       = (const float*)d_in[2];
    const float* embedding = (const float*)d_in[3];
    const float* attn_w    = (const float*)d_in[4];
    const float* attn_b    = (const float*)d_in[5];
    const float* comb_w    = (const float*)d_in[6];
    const float* comb_b    = (const float*)d_in[7];
    const float* w_ih      = (const float*)d_in[8];
    const float* w_hh      = (const float*)d_in[9];
    const float* b_ih      = (const float*)d_in[10];
    const float* b_hh      = (const float*)d_in[11];
    const float* out_w     = (const float*)d_in[12];
    const float* out_b     = (const float*)d_in[13];
    float* out = (float*)d_out;

    // output layout: [log_softmax (V)] [h_new (H)] [attn_weights (L)]
    k_attn     <<<L / 8, 256>>>(tok, hidden, embedding, attn_w, attn_b);
    k_attnapply<<<dim3(H / 256, NP), 256>>>(enc, out + V + H);
    k_comb     <<<E / 8, 256>>>(tok, embedding, comb_w, comb_b);
    k_gru      <<<G3 / 8, 256>>>(w_ih, w_hh, b_ih, b_hh, hidden);
    k_hnew     <<<H / 256, 256>>>(hidden, out + V);
    k_logits   <<<(V + 7) / 8, 256>>>(out_w, out_b);
    k_lse1     <<<64, 256>>>();
    k_out      <<<(V + 255) / 256, 256>>>(out);
}